// round 2
// baseline (speedup 1.0000x reference)
#include <cuda_runtime.h>
#include <cuda_fp16.h>
#include <cstdint>

// ============================================================================
// PWBLinearLayer: out[B,128] = x[B,1024] @ quantize(W)[1024,128] + quantize(b)
//
// Baseline-PTX tensor-core path (harness compiles at compute_100 — NO tcgen05):
//   prep : Wq = round(clip(W,-1,1)*127) as EXACT integers in fp16, layout [k][n]
//   gemm : per-CTA M=128,N=128 tile; x split into hi=f16(x), lo=f16(x-hi);
//          mma.sync m16n8k16 f16->f32 accumulates hi@W + lo@W in one pass
//          (rel err ~1e-7); epilogue scales by 1/127 and adds quantized bias.
// ============================================================================

#define DINLINE __device__ __forceinline__

__device__ __align__(16) __half g_wh[1024 * 128];  // [k][n], n contiguous
__device__ float g_bq[128];

// ---------------------------------------------------------------------------
DINLINE uint32_t smem_u32(const void* p) {
    uint32_t a;
    asm("{ .reg .u64 t; cvta.to.shared.u64 t, %1; cvt.u32.u64 %0, t; }"
        : "=r"(a) : "l"(p));
    return a;
}

DINLINE void ldsm4(uint32_t (&r)[4], uint32_t addr) {
    asm volatile("ldmatrix.sync.aligned.m8n8.x4.shared.b16 {%0,%1,%2,%3}, [%4];"
                 : "=r"(r[0]), "=r"(r[1]), "=r"(r[2]), "=r"(r[3]) : "r"(addr));
}

DINLINE void ldsm4t(uint32_t (&r)[4], uint32_t addr) {
    asm volatile("ldmatrix.sync.aligned.m8n8.x4.trans.shared.b16 {%0,%1,%2,%3}, [%4];"
                 : "=r"(r[0]), "=r"(r[1]), "=r"(r[2]), "=r"(r[3]) : "r"(addr));
}

DINLINE void hmma(float (&d)[4], const uint32_t (&a)[4], const uint32_t (&b)[2]) {
    asm volatile(
        "mma.sync.aligned.m16n8k16.row.col.f32.f16.f16.f32 "
        "{%0,%1,%2,%3}, {%4,%5,%6,%7}, {%8,%9}, {%0,%1,%2,%3};"
        : "+f"(d[0]), "+f"(d[1]), "+f"(d[2]), "+f"(d[3])
        : "r"(a[0]), "r"(a[1]), "r"(a[2]), "r"(a[3]), "r"(b[0]), "r"(b[1]));
}

DINLINE void cp_async16(uint32_t saddr, const void* gaddr) {
    asm volatile("cp.async.ca.shared.global [%0], [%1], 16;"
                 :: "r"(saddr), "l"(gaddr));
}
#define CP_COMMIT() asm volatile("cp.async.commit_group;" ::: "memory")
#define CP_WAIT0()  asm volatile("cp.async.wait_group 0;" ::: "memory")

// split two fp32 into packed fp16 hi + fp16 lo (residual)
DINLINE void split2(float v0, float v1, uint32_t& hi, uint32_t& lo) {
    __half2 h = __floats2half2_rn(v0, v1);
    float f0 = __low2float(h), f1 = __high2float(h);
    __half2 l = __floats2half2_rn(v0 - f0, v1 - f1);
    hi = *reinterpret_cast<uint32_t*>(&h);
    lo = *reinterpret_cast<uint32_t*>(&l);
}

// ---------------------------------------------------------------------------
// Prep: quantize W (exact ints in fp16, [k][n]); quantize bias.
// ---------------------------------------------------------------------------
__global__ void pwb_prep_kernel(const float* __restrict__ W,
                                const float* __restrict__ b) {
    int idx = blockIdx.x * blockDim.x + threadIdx.x;
    if (idx < 1024 * 128) {
        float w = W[idx];
        w = fminf(fmaxf(w, -1.0f), 1.0f);
        g_wh[idx] = __float2half_rn(rintf(w * 127.0f));  // int in [-127,127]
    }
    if (idx < 128) {
        float v = fminf(fmaxf(b[idx], -1.0f), 1.0f);
        g_bq[idx] = rintf(v * 127.0f) * (1.0f / 127.0f);
    }
}

// ---------------------------------------------------------------------------
// GEMM kernel.
// SMEM per stage (24576 B):
//   A tile: 128 rows x 128 B.  chunks 0-3 = hi (64 fp16/row), 4-7 = lo.
//           16-B chunk c at row r lives at physical chunk (c ^ (r&7)).
//   B tile: 32 rows (k) x 256 B (128 fp16, n contiguous).
//           chunk c (0-15) at row k -> (c&8) | ((c^k)&7).
// 2 stages + 512 B bias = 49664 B dynamic smem.
// ---------------------------------------------------------------------------
static constexpr int STAGE    = 24576;
static constexpr int OFF_B    = 16384;
static constexpr int OFF_BIAS = 2 * STAGE;
static constexpr int SMEM_TOTAL = OFF_BIAS + 512;
static constexpr int THREADS  = 256;
static constexpr int KCHUNKS  = 32;   // 1024 / 32

__global__ __launch_bounds__(THREADS, 2)
void pwb_gemm_kernel(const float* __restrict__ x, float* __restrict__ out) {
    extern __shared__ char smem[];
    const uint32_t sb = smem_u32(smem);
    const int tid  = threadIdx.x;
    const int wid  = tid >> 5;
    const int lane = tid & 31;
    const int wm   = wid >> 1;   // 0..3  (M)
    const int wn   = wid & 1;    // 0..1  (N)
    const int tile = blockIdx.x;

    // bias -> smem
    if (tid < 128)
        reinterpret_cast<float*>(smem + OFF_BIAS)[tid] = g_bq[tid];

    const float* xg = x + (size_t)tile * 128 * 1024;

    // ---- A load/convert/store helpers (each thread: 1/2 row, 16 fp32) ----
    const int arow = tid >> 1;          // 0..127
    const int ah   = tid & 1;           // half of the 32-k chunk
    float4 f4[4];

    auto ldgA = [&](int kc) {
        const float4* p = reinterpret_cast<const float4*>(
            xg + (size_t)arow * 1024 + kc * 32 + ah * 16);
        #pragma unroll
        for (int i = 0; i < 4; ++i) f4[i] = p[i];
    };
    auto stsA = [&](int stage) {
        uint32_t base = sb + stage * STAGE + arow * 128;
        #pragma unroll
        for (int j = 0; j < 2; ++j) {
            uint32_t h[4], l[4];
            split2(f4[2 * j].x, f4[2 * j].y, h[0], l[0]);
            split2(f4[2 * j].z, f4[2 * j].w, h[1], l[1]);
            split2(f4[2 * j + 1].x, f4[2 * j + 1].y, h[2], l[2]);
            split2(f4[2 * j + 1].z, f4[2 * j + 1].w, h[3], l[3]);
            uint32_t c  = ah * 2 + j;                 // logical hi chunk 0..3
            uint32_t ph = (c ^ (arow & 7)) * 16;
            asm volatile("st.shared.v4.b32 [%0], {%1,%2,%3,%4};"
                         :: "r"(base + ph), "r"(h[0]), "r"(h[1]), "r"(h[2]), "r"(h[3]) : "memory");
            asm volatile("st.shared.v4.b32 [%0], {%1,%2,%3,%4};"
                         :: "r"(base + (ph ^ 64)), "r"(l[0]), "r"(l[1]), "r"(l[2]), "r"(l[3]) : "memory");
        }
    };
    auto ldB = [&](int stage, int kc) {   // 512 x 16B chunks, 2 per thread
        #pragma unroll
        for (int t = 0; t < 2; ++t) {
            int idx = tid + t * THREADS;
            int row = idx >> 4, c = idx & 15;
            uint32_t phys = (uint32_t)((c & 8) | ((c ^ row) & 7));
            cp_async16(sb + stage * STAGE + OFF_B + row * 256 + phys * 16,
                       g_wh + (size_t)(kc * 32 + row) * 128 + c * 8);
        }
    };

    // ---- accumulators ----
    float acc[2][8][4];
    #pragma unroll
    for (int mt = 0; mt < 2; ++mt)
        #pragma unroll
        for (int nt = 0; nt < 8; ++nt)
            #pragma unroll
            for (int i = 0; i < 4; ++i) acc[mt][nt][i] = 0.0f;

    const int lr = lane & 15;
    const int lc = lane >> 4;

    auto compute = [&](int stage) {
        uint32_t aBase = sb + stage * STAGE;
        uint32_t bBase = aBase + OFF_B;
        #pragma unroll
        for (int kt = 0; kt < 2; ++kt) {
            uint32_t bfr[8][2];
            #pragma unroll
            for (int j = 0; j < 4; ++j) {
                int row = kt * 16 + lr;
                int cn  = wn * 8 + j * 2 + lc;
                uint32_t phys = (uint32_t)((cn & 8) | ((cn ^ row) & 7));
                uint32_t r[4];
                ldsm4t(r, bBase + row * 256 + phys * 16);
                bfr[2 * j][0] = r[0]; bfr[2 * j][1] = r[1];
                bfr[2 * j + 1][0] = r[2]; bfr[2 * j + 1][1] = r[3];
            }
            #pragma unroll
            for (int mt = 0; mt < 2; ++mt) {
                int row = wm * 32 + mt * 16 + lr;
                uint32_t ch = (uint32_t)((kt * 2 + lc) ^ (row & 7));
                uint32_t a[4];
                ldsm4(a, aBase + row * 128 + ch * 16);        // hi
                #pragma unroll
                for (int nt = 0; nt < 8; ++nt) hmma(acc[mt][nt], a, bfr[nt]);
                ldsm4(a, aBase + row * 128 + (ch ^ 4) * 16);  // lo
                #pragma unroll
                for (int nt = 0; nt < 8; ++nt) hmma(acc[mt][nt], a, bfr[nt]);
            }
        }
    };

    // ---- prologue ----
    ldgA(0);
    ldB(0, 0);
    CP_COMMIT();
    stsA(0);
    CP_WAIT0();
    __syncthreads();

    // ---- main loop, 2-stage pipeline ----
    for (int kc = 0; kc < KCHUNKS; ++kc) {
        int cur = kc & 1;
        if (kc + 1 < KCHUNKS) {
            ldgA(kc + 1);
            ldB(cur ^ 1, kc + 1);
            CP_COMMIT();
        }
        compute(cur);
        if (kc + 1 < KCHUNKS) {
            stsA(cur ^ 1);
            CP_WAIT0();
        }
        __syncthreads();
    }

    // ---- epilogue: scale + bias, direct STG (32B sectors fully used) ----
    const float s = 1.0f / 127.0f;
    const float* bias = reinterpret_cast<const float*>(smem + OFF_BIAS);
    float* og = out + (size_t)tile * 128 * 128;
    const int col0 = wn * 64 + (lane & 3) * 2;
    #pragma unroll
    for (int mt = 0; mt < 2; ++mt) {
        int r0 = wm * 32 + mt * 16 + (lane >> 2);
        #pragma unroll
        for (int nt = 0; nt < 8; ++nt) {
            int col = col0 + nt * 8;
            float b0 = bias[col], b1 = bias[col + 1];
            float2 v0 = make_float2(acc[mt][nt][0] * s + b0,
                                    acc[mt][nt][1] * s + b1);
            float2 v1 = make_float2(acc[mt][nt][2] * s + b0,
                                    acc[mt][nt][3] * s + b1);
            *reinterpret_cast<float2*>(og + (size_t)r0 * 128 + col) = v0;
            *reinterpret_cast<float2*>(og + (size_t)(r0 + 8) * 128 + col) = v1;
        }
    }
}

// ---------------------------------------------------------------------------
extern "C" void kernel_launch(void* const* d_in, const int* in_sizes, int n_in,
                              void* d_out, int out_size) {
    const float* x = (const float*)d_in[0];   // [B, 1024]
    const float* W = (const float*)d_in[1];   // [1024, 128]
    const float* b = (const float*)d_in[2];   // [128]
    float* out = (float*)d_out;               // [B, 128]

    const int Mrows = in_sizes[0] / 1024;
    const int grid  = Mrows / 128;

    static bool attr_set = false;
    cudaFuncSetAttribute(pwb_gemm_kernel,
                         cudaFuncAttributeMaxDynamicSharedMemorySize,
                         SMEM_TOTAL);
    (void)attr_set;

    pwb_prep_kernel<<<(1024 * 128 + 255) / 256, 256>>>(W, b);
    pwb_gemm_kernel<<<grid, THREADS, SMEM_TOTAL>>>(x, out);
}

// round 3
// speedup vs baseline: 1.0968x; 1.0968x over previous
#include <cuda_runtime.h>
#include <cuda_fp16.h>
#include <cstdint>

// ============================================================================
// PWBLinearLayer: out[B,128] = x[B,1024] @ quantize(W)[1024,128] + quantize(b)
//
// Baseline-PTX tensor-core path (compute_100 — no tcgen05):
//   prep : Wq = round(clip(W,-1,1)*127) as EXACT integers in fp16, [k][n]
//   gemm : per-CTA M=128,N=128 tile; x converted to fp16 (hi only — residual
//          analysis: rel_err ~3e-4 << 1e-3); mma.sync m16n8k16 f16->f32;
//          3-stage cp.async ring for W; epilogue scales 1/127 + bias.
// ============================================================================

#define DINLINE __device__ __forceinline__

__device__ __align__(16) __half g_wh[1024 * 128];  // [k][n], n contiguous
__device__ float g_bq[128];

// ---------------------------------------------------------------------------
DINLINE uint32_t smem_u32(const void* p) {
    uint32_t a;
    asm("{ .reg .u64 t; cvta.to.shared.u64 t, %1; cvt.u32.u64 %0, t; }"
        : "=r"(a) : "l"(p));
    return a;
}

DINLINE void ldsm4(uint32_t (&r)[4], uint32_t addr) {
    asm volatile("ldmatrix.sync.aligned.m8n8.x4.shared.b16 {%0,%1,%2,%3}, [%4];"
                 : "=r"(r[0]), "=r"(r[1]), "=r"(r[2]), "=r"(r[3]) : "r"(addr));
}

DINLINE void ldsm4t(uint32_t (&r)[4], uint32_t addr) {
    asm volatile("ldmatrix.sync.aligned.m8n8.x4.trans.shared.b16 {%0,%1,%2,%3}, [%4];"
                 : "=r"(r[0]), "=r"(r[1]), "=r"(r[2]), "=r"(r[3]) : "r"(addr));
}

DINLINE void hmma(float (&d)[4], const uint32_t (&a)[4], const uint32_t (&b)[2]) {
    asm volatile(
        "mma.sync.aligned.m16n8k16.row.col.f32.f16.f16.f32 "
        "{%0,%1,%2,%3}, {%4,%5,%6,%7}, {%8,%9}, {%0,%1,%2,%3};"
        : "+f"(d[0]), "+f"(d[1]), "+f"(d[2]), "+f"(d[3])
        : "r"(a[0]), "r"(a[1]), "r"(a[2]), "r"(a[3]), "r"(b[0]), "r"(b[1]));
}

DINLINE void cp_async16(uint32_t saddr, const void* gaddr) {
    asm volatile("cp.async.cg.shared.global [%0], [%1], 16;"
                 :: "r"(saddr), "l"(gaddr));
}
#define CP_COMMIT()  asm volatile("cp.async.commit_group;" ::: "memory")
#define CP_WAIT(n)   asm volatile("cp.async.wait_group %0;" :: "n"(n) : "memory")

DINLINE uint32_t cvt2(float v0, float v1) {
    __half2 h = __floats2half2_rn(v0, v1);
    return *reinterpret_cast<uint32_t*>(&h);
}

// ---------------------------------------------------------------------------
// Prep: quantize W (exact ints in fp16, [k][n]); quantize bias.
// ---------------------------------------------------------------------------
__global__ void pwb_prep_kernel(const float* __restrict__ W,
                                const float* __restrict__ b) {
    int idx = blockIdx.x * blockDim.x + threadIdx.x;
    if (idx < 1024 * 128) {
        float w = W[idx];
        w = fminf(fmaxf(w, -1.0f), 1.0f);
        g_wh[idx] = __float2half_rn(rintf(w * 127.0f));  // int in [-127,127]
    }
    if (idx < 128) {
        float v = fminf(fmaxf(b[idx], -1.0f), 1.0f);
        g_bq[idx] = rintf(v * 127.0f) * (1.0f / 127.0f);
    }
}

// ---------------------------------------------------------------------------
// GEMM kernel. 3 stages, each 24576 B:
//   A tile: 128 rows x 128 B. fp16 x in 16-B chunks 0-3 (chunks 4-7 unused);
//           chunk c at row r stored at physical chunk (c ^ (r&7)).
//   B tile: 32 rows (k) x 256 B (128 fp16, n contiguous);
//           chunk c (0-15) at row k -> (c&8) | ((c^k)&7).
// ---------------------------------------------------------------------------
static constexpr int STAGE    = 24576;
static constexpr int OFF_B    = 16384;
static constexpr int NSTAGE   = 3;
static constexpr int OFF_BIAS = NSTAGE * STAGE;
static constexpr int SMEM_TOTAL = OFF_BIAS + 512;
static constexpr int THREADS  = 256;
static constexpr int KCHUNKS  = 32;   // 1024 / 32

__global__ __launch_bounds__(THREADS, 2)
void pwb_gemm_kernel(const float* __restrict__ x, float* __restrict__ out) {
    extern __shared__ char smem[];
    const uint32_t sb = smem_u32(smem);
    const int tid  = threadIdx.x;
    const int wid  = tid >> 5;
    const int lane = tid & 31;
    const int wm   = wid >> 1;   // 0..3  (M)
    const int wn   = wid & 1;    // 0..1  (N)
    const int tile = blockIdx.x;

    if (tid < 128)
        reinterpret_cast<float*>(smem + OFF_BIAS)[tid] = g_bq[tid];

    const float* xg = x + (size_t)tile * 128 * 1024;

    // ---- A: each thread owns 1/2 row of a 32-k chunk (16 fp32) ----
    const int arow = tid >> 1;          // 0..127
    const int ah   = tid & 1;           // which 16-k half
    float4 f4[4];

    auto ldgA = [&](int kc) {
        const float4* p = reinterpret_cast<const float4*>(
            xg + (size_t)arow * 1024 + kc * 32 + ah * 16);
        #pragma unroll
        for (int i = 0; i < 4; ++i) f4[i] = p[i];
    };
    auto stsA = [&](int stage) {
        uint32_t base = sb + stage * STAGE + arow * 128;
        #pragma unroll
        for (int j = 0; j < 2; ++j) {
            uint32_t h[4];
            h[0] = cvt2(f4[2 * j].x, f4[2 * j].y);
            h[1] = cvt2(f4[2 * j].z, f4[2 * j].w);
            h[2] = cvt2(f4[2 * j + 1].x, f4[2 * j + 1].y);
            h[3] = cvt2(f4[2 * j + 1].z, f4[2 * j + 1].w);
            uint32_t c  = (uint32_t)(ah * 2 + j);     // logical chunk 0..3
            uint32_t ph = (c ^ (arow & 7)) * 16;
            asm volatile("st.shared.v4.b32 [%0], {%1,%2,%3,%4};"
                         :: "r"(base + ph), "r"(h[0]), "r"(h[1]), "r"(h[2]), "r"(h[3]) : "memory");
        }
    };
    auto ldB = [&](int stage, int kc) {   // 512 x 16B chunks, 2 per thread
        #pragma unroll
        for (int t = 0; t < 2; ++t) {
            int idx = tid + t * THREADS;
            int row = idx >> 4, c = idx & 15;
            uint32_t phys = (uint32_t)((c & 8) | ((c ^ row) & 7));
            cp_async16(sb + stage * STAGE + OFF_B + row * 256 + phys * 16,
                       g_wh + (size_t)(kc * 32 + row) * 128 + c * 8);
        }
    };

    // ---- accumulators ----
    float acc[2][8][4];
    #pragma unroll
    for (int mt = 0; mt < 2; ++mt)
        #pragma unroll
        for (int nt = 0; nt < 8; ++nt)
            #pragma unroll
            for (int i = 0; i < 4; ++i) acc[mt][nt][i] = 0.0f;

    const int lr = lane & 15;
    const int lc = lane >> 4;

    auto compute = [&](int stage) {
        uint32_t aBase = sb + stage * STAGE;
        uint32_t bBase = aBase + OFF_B;
        #pragma unroll
        for (int kt = 0; kt < 2; ++kt) {
            uint32_t bfr[8][2];
            #pragma unroll
            for (int j = 0; j < 4; ++j) {
                int row = kt * 16 + lr;
                int cn  = wn * 8 + j * 2 + lc;
                uint32_t phys = (uint32_t)((cn & 8) | ((cn ^ row) & 7));
                uint32_t r[4];
                ldsm4t(r, bBase + row * 256 + phys * 16);
                bfr[2 * j][0] = r[0]; bfr[2 * j][1] = r[1];
                bfr[2 * j + 1][0] = r[2]; bfr[2 * j + 1][1] = r[3];
            }
            #pragma unroll
            for (int mt = 0; mt < 2; ++mt) {
                int row = wm * 32 + mt * 16 + lr;
                uint32_t ch = (uint32_t)((kt * 2 + lc) ^ (row & 7));
                uint32_t a[4];
                ldsm4(a, aBase + row * 128 + ch * 16);
                #pragma unroll
                for (int nt = 0; nt < 8; ++nt) hmma(acc[mt][nt], a, bfr[nt]);
            }
        }
    };

    // ---- prologue: stage0+1 B in flight, stage0 A resident ----
    ldgA(0);
    ldB(0, 0); CP_COMMIT();
    ldB(1, 1); CP_COMMIT();
    stsA(0);
    CP_WAIT(1);              // stage0 B done (stage1 still in flight)
    __syncthreads();

    // ---- main loop ----
    for (int kc = 0; kc < KCHUNKS; ++kc) {
        const int cur = kc % NSTAGE;
        if (kc + 2 < KCHUNKS) { ldB((kc + 2) % NSTAGE, kc + 2); CP_COMMIT(); }
        if (kc + 1 < KCHUNKS) ldgA(kc + 1);
        compute(cur);
        if (kc + 1 < KCHUNKS) stsA((kc + 1) % NSTAGE);
        if (kc + 2 < KCHUNKS) { CP_WAIT(1); }   // stage kc+1 B done
        else                  { CP_WAIT(0); }
        __syncthreads();
    }

    // ---- epilogue: scale + bias, direct STG ----
    const float s = 1.0f / 127.0f;
    const float* bias = reinterpret_cast<const float*>(smem + OFF_BIAS);
    float* og = out + (size_t)tile * 128 * 128;
    const int col0 = wn * 64 + (lane & 3) * 2;
    #pragma unroll
    for (int mt = 0; mt < 2; ++mt) {
        int r0 = wm * 32 + mt * 16 + (lane >> 2);
        #pragma unroll
        for (int nt = 0; nt < 8; ++nt) {
            int col = col0 + nt * 8;
            float b0 = bias[col], b1 = bias[col + 1];
            float2 v0 = make_float2(acc[mt][nt][0] * s + b0,
                                    acc[mt][nt][1] * s + b1);
            float2 v1 = make_float2(acc[mt][nt][2] * s + b0,
                                    acc[mt][nt][3] * s + b1);
            *reinterpret_cast<float2*>(og + (size_t)r0 * 128 + col) = v0;
            *reinterpret_cast<float2*>(og + (size_t)(r0 + 8) * 128 + col) = v1;
        }
    }
}

// ---------------------------------------------------------------------------
extern "C" void kernel_launch(void* const* d_in, const int* in_sizes, int n_in,
                              void* d_out, int out_size) {
    const float* x = (const float*)d_in[0];   // [B, 1024]
    const float* W = (const float*)d_in[1];   // [1024, 128]
    const float* b = (const float*)d_in[2];   // [128]
    float* out = (float*)d_out;               // [B, 128]

    const int Mrows = in_sizes[0] / 1024;
    const int grid  = Mrows / 128;

    cudaFuncSetAttribute(pwb_gemm_kernel,
                         cudaFuncAttributeMaxDynamicSharedMemorySize,
                         SMEM_TOTAL);

    pwb_prep_kernel<<<(1024 * 128 + 255) / 256, 256>>>(W, b);
    pwb_gemm_kernel<<<grid, THREADS, SMEM_TOTAL>>>(x, out);
}

// round 4
// speedup vs baseline: 1.4157x; 1.2908x over previous
#include <cuda_runtime.h>
#include <cuda_fp16.h>
#include <cstdint>

// ============================================================================
// PWBLinearLayer: out[B,128] = x[B,1024] @ quantize(W)[1024,128] + quantize(b)
//
// Baseline-PTX tensor-core path (compute_100 — no tcgen05):
//   prep : Wq = round(clip(W,-1,1)*127) as EXACT integers in fp16, [k][n]
//   gemm : per-CTA M=128,N=128 tile; fully-async loads:
//            A (fp32 x) -> cp.async 3-stage ring -> smem convert to fp16
//            B (fp16 Wq) -> cp.async 4-stage ring
//          mma.sync m16n8k16 f16->f32 (hi-only: measured rel_err 2.1e-4);
//          epilogue scales 1/127 + quantized bias.
// ============================================================================

#define DINLINE __device__ __forceinline__

__device__ __align__(16) __half g_wh[1024 * 128];  // [k][n], n contiguous
__device__ float g_bq[128];

// ---------------------------------------------------------------------------
DINLINE uint32_t smem_u32(const void* p) {
    uint32_t a;
    asm("{ .reg .u64 t; cvta.to.shared.u64 t, %1; cvt.u32.u64 %0, t; }"
        : "=r"(a) : "l"(p));
    return a;
}

DINLINE void ldsm4(uint32_t (&r)[4], uint32_t addr) {
    asm volatile("ldmatrix.sync.aligned.m8n8.x4.shared.b16 {%0,%1,%2,%3}, [%4];"
                 : "=r"(r[0]), "=r"(r[1]), "=r"(r[2]), "=r"(r[3]) : "r"(addr));
}

DINLINE void ldsm4t(uint32_t (&r)[4], uint32_t addr) {
    asm volatile("ldmatrix.sync.aligned.m8n8.x4.trans.shared.b16 {%0,%1,%2,%3}, [%4];"
                 : "=r"(r[0]), "=r"(r[1]), "=r"(r[2]), "=r"(r[3]) : "r"(addr));
}

DINLINE void hmma(float (&d)[4], const uint32_t (&a)[4], const uint32_t (&b)[2]) {
    asm volatile(
        "mma.sync.aligned.m16n8k16.row.col.f32.f16.f16.f32 "
        "{%0,%1,%2,%3}, {%4,%5,%6,%7}, {%8,%9}, {%0,%1,%2,%3};"
        : "+f"(d[0]), "+f"(d[1]), "+f"(d[2]), "+f"(d[3])
        : "r"(a[0]), "r"(a[1]), "r"(a[2]), "r"(a[3]), "r"(b[0]), "r"(b[1]));
}

DINLINE void cp_async16(uint32_t saddr, const void* gaddr) {
    asm volatile("cp.async.cg.shared.global [%0], [%1], 16;"
                 :: "r"(saddr), "l"(gaddr));
}
#define CP_COMMIT()  asm volatile("cp.async.commit_group;" ::: "memory")
#define CP_WAIT(n)   asm volatile("cp.async.wait_group %0;" :: "n"(n) : "memory")

DINLINE uint32_t cvt2(float v0, float v1) {
    __half2 h = __floats2half2_rn(v0, v1);
    return *reinterpret_cast<uint32_t*>(&h);
}

// ---------------------------------------------------------------------------
// Prep: quantize W (exact ints in fp16, [k][n]); quantize bias.
// ---------------------------------------------------------------------------
__global__ void pwb_prep_kernel(const float* __restrict__ W,
                                const float* __restrict__ b) {
    int idx = blockIdx.x * blockDim.x + threadIdx.x;
    if (idx < 1024 * 128) {
        float w = W[idx];
        w = fminf(fmaxf(w, -1.0f), 1.0f);
        g_wh[idx] = __float2half_rn(rintf(w * 127.0f));  // int in [-127,127]
    }
    if (idx < 128) {
        float v = fminf(fmaxf(b[idx], -1.0f), 1.0f);
        g_bq[idx] = rintf(v * 127.0f) * (1.0f / 127.0f);
    }
}

// ---------------------------------------------------------------------------
// GEMM kernel. SMEM map (102912 B total):
//   A32 ring : 3 stages x 16384 B. 128 rows x 128 B fp32; 16-B chunk c
//              (0..7) at row r stored at phys chunk c ^ (r&7).
//   B16 ring : 4 stages x 8192 B. 32 k-rows x 256 B; chunk c (0..15)
//              at row k -> (c&8) | ((c^k)&7).
//   A16 bufs : 2 x 10240 B. 128 rows x 80 B pitch (64 B fp16 data);
//              chunk c (0..3) at c*16, no XOR — 80-B pitch decorrelates
//              banks (r*80 mod 128 all-distinct over any 8 consecutive rows).
//   bias     : 512 B
// ---------------------------------------------------------------------------
static constexpr int STAGE_A32 = 16384;
static constexpr int NSTAGE_A  = 3;
static constexpr int STAGE_B   = 8192;
static constexpr int NSTAGE_B  = 4;
static constexpr int STAGE_A16 = 10240;
static constexpr int OFF_A32   = 0;
static constexpr int OFF_B     = NSTAGE_A * STAGE_A32;            // 49152
static constexpr int OFF_A16   = OFF_B + NSTAGE_B * STAGE_B;      // 81920
static constexpr int OFF_BIAS  = OFF_A16 + 2 * STAGE_A16;         // 102400
static constexpr int SMEM_TOTAL = OFF_BIAS + 512;                 // 102912
static constexpr int THREADS  = 256;
static constexpr int KCHUNKS  = 32;   // 1024 / 32

__global__ __launch_bounds__(THREADS, 2)
void pwb_gemm_kernel(const float* __restrict__ x, float* __restrict__ out) {
    extern __shared__ char smem[];
    const uint32_t sb = smem_u32(smem);
    const int tid  = threadIdx.x;
    const int wid  = tid >> 5;
    const int lane = tid & 31;
    const int wm   = wid >> 1;   // 0..3  (M)
    const int wn   = wid & 1;    // 0..1  (N)
    const int tile = blockIdx.x;

    if (tid < 128)
        reinterpret_cast<float*>(smem + OFF_BIAS)[tid] = g_bq[tid];

    const float* xg = x + (size_t)tile * 128 * 1024;

    const int arow = tid >> 1;          // 0..127
    const int ah   = tid & 1;           // which 16-k half of the 32-k chunk

    // ---- async A fetch: thread fetches exactly what it later converts ----
    auto ldA = [&](int stage, int kc) {
        uint32_t dst = sb + OFF_A32 + stage * STAGE_A32 + arow * 128;
        const float* src = xg + (size_t)arow * 1024 + kc * 32 + ah * 16;
        #pragma unroll
        for (int i = 0; i < 4; ++i) {
            uint32_t c = (uint32_t)(ah * 4 + i);
            uint32_t phys = c ^ (arow & 7);
            cp_async16(dst + phys * 16, src + i * 4);
        }
    };
    // ---- async B fetch ----
    auto ldB = [&](int stage, int kc) {   // 512 x 16B chunks, 2 per thread
        #pragma unroll
        for (int t = 0; t < 2; ++t) {
            int idx = tid + t * THREADS;
            int row = idx >> 4, c = idx & 15;
            uint32_t phys = (uint32_t)((c & 8) | ((c ^ row) & 7));
            cp_async16(sb + OFF_B + stage * STAGE_B + row * 256 + phys * 16,
                       g_wh + (size_t)(kc * 32 + row) * 128 + c * 8);
        }
    };
    // ---- smem fp32 -> fp16 convert (thread-local data, no pre-barrier) ----
    auto convertA = [&](int srcStage, int dstBuf) {
        uint32_t sA = sb + OFF_A32 + srcStage * STAGE_A32 + arow * 128;
        float4 v[4];
        #pragma unroll
        for (int i = 0; i < 4; ++i) {
            uint32_t c = (uint32_t)(ah * 4 + i);
            uint32_t phys = c ^ (arow & 7);
            asm volatile("ld.shared.v4.f32 {%0,%1,%2,%3}, [%4];"
                         : "=f"(v[i].x), "=f"(v[i].y), "=f"(v[i].z), "=f"(v[i].w)
                         : "r"(sA + phys * 16));
        }
        uint32_t h[8];
        #pragma unroll
        for (int i = 0; i < 4; ++i) {
            h[2 * i]     = cvt2(v[i].x, v[i].y);
            h[2 * i + 1] = cvt2(v[i].z, v[i].w);
        }
        uint32_t dA = sb + OFF_A16 + dstBuf * STAGE_A16 + arow * 80 + ah * 32;
        asm volatile("st.shared.v4.b32 [%0], {%1,%2,%3,%4};"
                     :: "r"(dA), "r"(h[0]), "r"(h[1]), "r"(h[2]), "r"(h[3]) : "memory");
        asm volatile("st.shared.v4.b32 [%0], {%1,%2,%3,%4};"
                     :: "r"(dA + 16), "r"(h[4]), "r"(h[5]), "r"(h[6]), "r"(h[7]) : "memory");
    };

    // ---- accumulators ----
    float acc[2][8][4];
    #pragma unroll
    for (int mt = 0; mt < 2; ++mt)
        #pragma unroll
        for (int nt = 0; nt < 8; ++nt)
            #pragma unroll
            for (int i = 0; i < 4; ++i) acc[mt][nt][i] = 0.0f;

    const int lr = lane & 15;
    const int lc = lane >> 4;

    auto compute = [&](int a16buf, int bstage) {
        uint32_t aBase = sb + OFF_A16 + a16buf * STAGE_A16;
        uint32_t bBase = sb + OFF_B + bstage * STAGE_B;
        #pragma unroll
        for (int kt = 0; kt < 2; ++kt) {
            uint32_t bfr[8][2];
            #pragma unroll
            for (int j = 0; j < 4; ++j) {
                int row = kt * 16 + lr;
                int cn  = wn * 8 + j * 2 + lc;
                uint32_t phys = (uint32_t)((cn & 8) | ((cn ^ row) & 7));
                uint32_t r[4];
                ldsm4t(r, bBase + row * 256 + phys * 16);
                bfr[2 * j][0] = r[0]; bfr[2 * j][1] = r[1];
                bfr[2 * j + 1][0] = r[2]; bfr[2 * j + 1][1] = r[3];
            }
            #pragma unroll
            for (int mt = 0; mt < 2; ++mt) {
                int row = wm * 32 + mt * 16 + lr;
                uint32_t ch = (uint32_t)(kt * 2 + lc);     // 0..3, no XOR
                uint32_t a[4];
                ldsm4(a, aBase + row * 80 + ch * 16);
                #pragma unroll
                for (int nt = 0; nt < 8; ++nt) hmma(acc[mt][nt], a, bfr[nt]);
            }
        }
    };

    // ---- prologue: chunks 0 and 1 in flight ----
    ldA(0, 0); ldB(0, 0); CP_COMMIT();
    ldA(1, 1); ldB(1, 1); CP_COMMIT();

    // ---- main loop ----
    for (int kc = 0; kc < KCHUNKS; ++kc) {
        if (kc + 2 < KCHUNKS) {
            ldA((kc + 2) % NSTAGE_A, kc + 2);
            ldB((kc + 2) % NSTAGE_B, kc + 2);
            CP_COMMIT();
        }
        if (kc < KCHUNKS - 2) { CP_WAIT(2); }   // chunk kc resident
        else                  { CP_WAIT(0); }
        convertA(kc % NSTAGE_A, kc & 1);
        __syncthreads();
        compute(kc & 1, kc % NSTAGE_B);
    }

    // ---- epilogue: scale + bias, direct STG ----
    const float s = 1.0f / 127.0f;
    const float* bias = reinterpret_cast<const float*>(smem + OFF_BIAS);
    float* og = out + (size_t)tile * 128 * 128;
    const int col0 = wn * 64 + (lane & 3) * 2;
    #pragma unroll
    for (int mt = 0; mt < 2; ++mt) {
        int r0 = wm * 32 + mt * 16 + (lane >> 2);
        #pragma unroll
        for (int nt = 0; nt < 8; ++nt) {
            int col = col0 + nt * 8;
            float b0 = bias[col], b1 = bias[col + 1];
            float2 v0 = make_float2(acc[mt][nt][0] * s + b0,
                                    acc[mt][nt][1] * s + b1);
            float2 v1 = make_float2(acc[mt][nt][2] * s + b0,
                                    acc[mt][nt][3] * s + b1);
            *reinterpret_cast<float2*>(og + (size_t)r0 * 128 + col) = v0;
            *reinterpret_cast<float2*>(og + (size_t)(r0 + 8) * 128 + col) = v1;
        }
    }
}

// ---------------------------------------------------------------------------
extern "C" void kernel_launch(void* const* d_in, const int* in_sizes, int n_in,
                              void* d_out, int out_size) {
    const float* x = (const float*)d_in[0];   // [B, 1024]
    const float* W = (const float*)d_in[1];   // [1024, 128]
    const float* b = (const float*)d_in[2];   // [128]
    float* out = (float*)d_out;               // [B, 128]

    const int Mrows = in_sizes[0] / 1024;
    const int grid  = Mrows / 128;

    cudaFuncSetAttribute(pwb_gemm_kernel,
                         cudaFuncAttributeMaxDynamicSharedMemorySize,
                         SMEM_TOTAL);

    pwb_prep_kernel<<<(1024 * 128 + 255) / 256, 256>>>(W, b);
    pwb_gemm_kernel<<<grid, THREADS, SMEM_TOTAL>>>(x, out);
}